// round 1
// baseline (speedup 1.0000x reference)
#include <cuda_runtime.h>
#include <math.h>

#define BB 8
#define CIN 64
#define COUT 128
#define NPTS 32768
#define RES 32
#define NVOX (RES*RES*RES)
#define GEPS 1e-5f

// ---------------- scratch (static device globals; no allocation) -------------
__device__ float d_mean[BB*3];
__device__ float d_scale[BB];
__device__ float d_normc[BB*3*NPTS];
__device__ float d_grid0[BB*NVOX*CIN];    //  67 MB  [b][v][ci]
__device__ float d_cnt[BB*NVOX];
__device__ float d_grid1[BB*NVOX*COUT];   // 134 MB  [b][v][o]
__device__ float d_grid2[BB*NVOX*COUT];   // 134 MB
__device__ float d_pt[BB*NPTS*COUT];      // 134 MB  [b][n][o]
__device__ float d_wt1[CIN*27*COUT];      // [(ci*27+t)][o]
__device__ float d_wt2[COUT*27*COUT];
__device__ float d_ptw[CIN*COUT];         // [ci][o]
__device__ float d_gstats1[BB*8*2];
__device__ float d_cstats2[BB*COUT*2];
__device__ float d_ptstats[BB*8*2];
__device__ float d_A[BB*COUT];
__device__ float d_Bc[BB*COUT];
__device__ float d_ptA[BB*COUT];
__device__ float d_ptB[BB*COUT];

// ---------------- prep: weight transposes -----------------------------------
__global__ void k_prep(const float* __restrict__ w1, const float* __restrict__ w2,
                       const float* __restrict__ ptw) {
    int i = blockIdx.x * 256 + threadIdx.x;
    if (i < CIN*27*COUT) {           // wt1[(ci*27+t)*128+o] = w1[(o*CIN+ci)*27+t]
        int o = i & 127; int r = i >> 7; int ci = r / 27, t = r % 27;
        d_wt1[i] = w1[(o*CIN + ci)*27 + t];
    }
    if (i < COUT*27*COUT) {
        int o = i & 127; int r = i >> 7; int ci = r / 27, t = r % 27;
        d_wt2[i] = w2[(o*COUT + ci)*27 + t];
    }
    if (i < CIN*COUT) {              // ptw[ci*128+o] = pt_w[o*CIN+ci]
        int o = i & 127; int ci = i >> 7;
        d_ptw[i] = ptw[o*CIN + ci];
    }
}

__global__ void k_zero() {
    int i = blockIdx.x * 256 + threadIdx.x;   // 16,777,216 threads exactly
    d_grid0[i] = 0.f;
    if (i < BB*NVOX)   d_cnt[i] = 0.f;
    if (i < BB*8*2)    d_gstats1[i] = 0.f;
    if (i < BB*COUT*2) d_cstats2[i] = 0.f;
    if (i < BB*8*2)    d_ptstats[i] = 0.f;
}

// ---------------- voxelize coords --------------------------------------------
__global__ void k_mean(const float* __restrict__ coords) {
    int b = blockIdx.x;
    __shared__ float s[256];
    for (int d = 0; d < 3; d++) {
        float acc = 0.f;
        for (int n = threadIdx.x; n < NPTS; n += 256)
            acc += coords[(b*3 + d)*NPTS + n];
        s[threadIdx.x] = acc; __syncthreads();
        for (int o = 128; o > 0; o >>= 1) {
            if (threadIdx.x < o) s[threadIdx.x] += s[threadIdx.x + o];
            __syncthreads();
        }
        if (threadIdx.x == 0) d_mean[b*3 + d] = s[0] / (float)NPTS;
        __syncthreads();
    }
}

__global__ void k_scale(const float* __restrict__ coords) {
    int b = blockIdx.x;
    float mx = d_mean[b*3], my = d_mean[b*3+1], mz = d_mean[b*3+2];
    __shared__ float s[256];
    float m = 0.f;
    for (int n = threadIdx.x; n < NPTS; n += 256) {
        float x = coords[(b*3+0)*NPTS + n] - mx;
        float y = coords[(b*3+1)*NPTS + n] - my;
        float z = coords[(b*3+2)*NPTS + n] - mz;
        m = fmaxf(m, sqrtf(x*x + y*y + z*z));
    }
    s[threadIdx.x] = m; __syncthreads();
    for (int o = 128; o > 0; o >>= 1) {
        if (threadIdx.x < o) s[threadIdx.x] = fmaxf(s[threadIdx.x], s[threadIdx.x + o]);
        __syncthreads();
    }
    if (threadIdx.x == 0) d_scale[b] = s[0] * 2.f;
}

__global__ void k_norm(const float* __restrict__ coords) {
    int i = blockIdx.x * 256 + threadIdx.x;
    if (i >= BB*3*NPTS) return;
    int b = i / (3*NPTS); int d = (i / NPTS) % 3;
    float t = (coords[i] - d_mean[b*3 + d]) / d_scale[b] + 0.5f;
    d_normc[i] = fminf(fmaxf(t * (float)RES, 0.f), (float)(RES - 1));
}

// ---------------- scatter-mean voxelization ----------------------------------
__global__ void k_scatter(const float* __restrict__ feat) {
    int p = blockIdx.x * 256 + threadIdx.x;
    if (p >= BB*NPTS) return;
    int b = p >> 15, n = p & (NPTS - 1);
    int ix = min(max((int)rintf(d_normc[(b*3+0)*NPTS + n]), 0), RES-1);
    int iy = min(max((int)rintf(d_normc[(b*3+1)*NPTS + n]), 0), RES-1);
    int iz = min(max((int)rintf(d_normc[(b*3+2)*NPTS + n]), 0), RES-1);
    int vid = (ix*RES + iy)*RES + iz;
    float* row = &d_grid0[(long)(b*NVOX + vid) * CIN];
    #pragma unroll 4
    for (int c = 0; c < CIN; c++)
        atomicAdd(&row[c], feat[((long)(b*CIN) + c)*NPTS + n]);
    atomicAdd(&d_cnt[b*NVOX + vid], 1.f);
}

__global__ void k_div() {
    int i = blockIdx.x * 256 + threadIdx.x;   // B*NVOX*CIN threads
    float c = d_cnt[i / CIN];
    d_grid0[i] = d_grid0[i] / fmaxf(c, 1.f);
}

// ---------------- 3x3x3 conv, channels-last, z-line per block ----------------
// STAGE 0: grid0(CIN) -> grid1 with wt1; STAGE 1: grid1(COUT) -> grid2 with wt2
template<int CI, int STAGE>
__global__ void k_conv(const float* __restrict__ bias) {
    extern __shared__ float sm[];                      // [ci][xy][34]
    const float* __restrict__ gin  = (STAGE == 0) ? d_grid0 : d_grid1;
    float*       __restrict__ gout = (STAGE == 0) ? d_grid1 : d_grid2;
    const float* __restrict__ wt   = (STAGE == 0) ? d_wt1   : d_wt2;

    int blk = blockIdx.x;
    int b = blk >> 10, xr = (blk >> 5) & 31, yr = blk & 31;

    const int TOT = CI * 306;                          // 9 * 34 * CI
    for (int e = threadIdx.x; e < TOT; e += 256) {
        int ci = e % CI; int rest = e / CI;
        int zz = rest % 34; int xy = rest / 34;
        int gx = xr - 1 + xy / 3, gy = yr - 1 + xy % 3, gz = zz - 1;
        float v = 0.f;
        if (gx >= 0 && gx < RES && gy >= 0 && gy < RES && gz >= 0 && gz < RES)
            v = gin[((long)(b*NVOX) + (gx*RES + gy)*RES + gz) * CI + ci];
        sm[(ci*9 + xy)*34 + zz] = v;
    }
    __syncthreads();

    int o = threadIdx.x & 127, h = threadIdx.x >> 7, z0 = h * 16;
    float acc[16];
    float bv = bias[o];
    #pragma unroll
    for (int z = 0; z < 16; z++) acc[z] = bv;

    for (int ci = 0; ci < CI; ci++) {
        #pragma unroll 1
        for (int xy = 0; xy < 9; xy++) {
            const float* ip = &sm[(ci*9 + xy)*34 + z0];
            float inr[18];
            #pragma unroll
            for (int j = 0; j < 18; j++) inr[j] = ip[j];
            const float* wp = &wt[((ci*9 + xy)*3) * COUT + o];
            #pragma unroll
            for (int dz = 0; dz < 3; dz++) {
                float w = wp[dz * COUT];
                #pragma unroll
                for (int z = 0; z < 16; z++)
                    acc[z] = fmaf(w, inr[z + dz], acc[z]);
            }
        }
    }
    long base = ((long)(b*NVOX) + (xr*RES + yr)*RES + z0) * COUT + o;
    #pragma unroll
    for (int z = 0; z < 16; z++) gout[base + (long)z * COUT] = acc[z];
}

// ---------------- GN1 stats + normalize+swish --------------------------------
__global__ void k_gstats1() {
    int b = blockIdx.x >> 6, ch = blockIdx.x & 63;     // 512 voxels per chunk
    int c = threadIdx.x & 127, l2 = threadIdx.x >> 7;
    long base = ((long)b*NVOX + ch*512) * COUT;
    float s = 0.f, q = 0.f;
    for (int v = l2; v < 512; v += 2) {
        float x = d_grid1[base + (long)v*COUT + c];
        s += x; q += x*x;
    }
    __shared__ float ss[256], sq[256];
    ss[threadIdx.x] = s; sq[threadIdx.x] = q;
    __syncthreads();
    if (threadIdx.x < 8) {
        float S = 0.f, Q = 0.f;
        for (int j = 0; j < 16; j++) {
            int cc = threadIdx.x*16 + j;
            S += ss[cc] + ss[cc+128]; Q += sq[cc] + sq[cc+128];
        }
        atomicAdd(&d_gstats1[(b*8 + threadIdx.x)*2 + 0], S);
        atomicAdd(&d_gstats1[(b*8 + threadIdx.x)*2 + 1], Q);
    }
}

__global__ void k_gn1(const float* __restrict__ g, const float* __restrict__ bt) {
    int i = blockIdx.x * 256 + threadIdx.x;            // B*NVOX*COUT threads
    int c = i & 127; int b = i >> 22;                  // i/(NVOX*128) = i>>22
    int gr = c >> 4;
    float S = d_gstats1[(b*8 + gr)*2], Q = d_gstats1[(b*8 + gr)*2 + 1];
    const float cnt = (float)NVOX * 16.f;
    float mu = S / cnt; float var = Q / cnt - mu*mu;
    float rs = rsqrtf(var + GEPS);
    float y = (d_grid1[i] - mu) * rs * g[c] + bt[c];
    d_grid1[i] = y / (1.f + expf(-y));
}

// ---------------- GN2 per-channel stats (for GN + SE fold) -------------------
__global__ void k_cstats2() {
    int b = blockIdx.x >> 6, ch = blockIdx.x & 63;
    int c = threadIdx.x & 127, l2 = threadIdx.x >> 7;
    long base = ((long)b*NVOX + ch*512) * COUT;
    float s = 0.f, q = 0.f;
    for (int v = l2; v < 512; v += 2) {
        float x = d_grid2[base + (long)v*COUT + c];
        s += x; q += x*x;
    }
    __shared__ float ss[256], sq[256];
    ss[threadIdx.x] = s; sq[threadIdx.x] = q;
    __syncthreads();
    if (threadIdx.x < 128) {
        atomicAdd(&d_cstats2[(b*COUT + c)*2 + 0], ss[c] + ss[c+128]);
        atomicAdd(&d_cstats2[(b*COUT + c)*2 + 1], sq[c] + sq[c+128]);
    }
}

// ---------------- SE + fold GN2*SE into per-(b,c) affine ---------------------
__global__ void k_se(const float* __restrict__ w1, const float* __restrict__ b1,
                     const float* __restrict__ w2, const float* __restrict__ b2,
                     const float* __restrict__ gamma, const float* __restrict__ beta) {
    int b = blockIdx.x; int c = threadIdx.x;
    __shared__ float s[128], gmu[8], grs[8], s1[16];
    const float cnt = (float)NVOX;
    if (c < 8) {
        float S = 0.f, Q = 0.f;
        for (int j = 0; j < 16; j++) {
            S += d_cstats2[(b*COUT + c*16 + j)*2 + 0];
            Q += d_cstats2[(b*COUT + c*16 + j)*2 + 1];
        }
        float gc = cnt * 16.f;
        float mu = S / gc; float var = Q / gc - mu*mu;
        gmu[c] = mu; grs[c] = rsqrtf(var + GEPS);
    }
    __syncthreads();
    int gr = c >> 4;
    float mu = gmu[gr], rs = grs[gr];
    float csum = d_cstats2[(b*COUT + c)*2];
    s[c] = (csum / cnt - mu) * rs * gamma[c] + beta[c];   // pooled mean of gn2 out
    __syncthreads();
    if (c < 16) {
        float a = b1[c];
        for (int j = 0; j < 128; j++) a += w1[c*128 + j] * s[j];
        s1[c] = fmaxf(a, 0.f);
    }
    __syncthreads();
    float a2 = b2[c];
    for (int j = 0; j < 16; j++) a2 += w2[c*16 + j] * s1[j];
    float se = 1.f / (1.f + expf(-a2));
    float rg = rs * gamma[c];
    d_A [b*COUT + c] = rg * se;
    d_Bc[b*COUT + c] = (beta[c] - mu * rg) * se;
}

// ---------------- point branch 1x1 conv + stats ------------------------------
__global__ void k_pt(const float* __restrict__ feat, const float* __restrict__ ptb) {
    int blk = blockIdx.x;
    int b = blk >> 10, n0 = (blk & 1023) * 32;
    __shared__ float fs[CIN*32];       // [ci][nn]
    __shared__ float so[32*COUT];      // [nn][o]
    __shared__ float ss[256], sq[256];
    for (int e = threadIdx.x; e < CIN*32; e += 256) {
        int ci = e >> 5, nn = e & 31;
        fs[e] = feat[((long)(b*CIN) + ci)*NPTS + n0 + nn];
    }
    __syncthreads();
    int o = threadIdx.x & 127, h = threadIdx.x >> 7;
    float acc[16];
    float bv = ptb[o];
    #pragma unroll
    for (int j = 0; j < 16; j++) acc[j] = bv;
    for (int ci = 0; ci < CIN; ci++) {
        float w = d_ptw[ci*COUT + o];
        #pragma unroll
        for (int j = 0; j < 16; j++)
            acc[j] = fmaf(w, fs[ci*32 + h*16 + j], acc[j]);
    }
    float s = 0.f, q = 0.f;
    #pragma unroll
    for (int j = 0; j < 16; j++) {
        s += acc[j]; q += acc[j]*acc[j];
        so[(h*16 + j)*COUT + o] = acc[j];
    }
    ss[threadIdx.x] = s; sq[threadIdx.x] = q;
    __syncthreads();
    if (threadIdx.x < 8) {
        float S = 0.f, Q = 0.f;
        for (int j = 0; j < 16; j++) {
            int cc = threadIdx.x*16 + j;
            S += ss[cc] + ss[cc+128]; Q += sq[cc] + sq[cc+128];
        }
        atomicAdd(&d_ptstats[(b*8 + threadIdx.x)*2 + 0], S);
        atomicAdd(&d_ptstats[(b*8 + threadIdx.x)*2 + 1], Q);
    }
    for (int e = threadIdx.x; e < 32*COUT; e += 256) {
        int nn = e >> 7, oo = e & 127;
        d_pt[((long)(b*NPTS) + n0 + nn)*COUT + oo] = so[e];
    }
}

__global__ void k_ptab(const float* __restrict__ g, const float* __restrict__ bt) {
    int i = blockIdx.x * 256 + threadIdx.x;
    if (i >= BB*COUT) return;
    int b = i >> 7, c = i & 127, gr = c >> 4;
    const float cnt = 16.f * (float)NPTS;
    float S = d_ptstats[(b*8 + gr)*2], Q = d_ptstats[(b*8 + gr)*2 + 1];
    float mu = S / cnt, var = Q / cnt - mu*mu, rs = rsqrtf(var + GEPS);
    d_ptA[i] = rs * g[c];
    d_ptB[i] = bt[c] - mu * rs * g[c];
}

// ---------------- trilinear devoxelize + point add -> out --------------------
__global__ void k_out(float* __restrict__ out) {
    int p = blockIdx.x * 4 + (threadIdx.x >> 5);
    int lane = threadIdx.x & 31;
    int b = p >> 15, n = p & (NPTS - 1);
    float nx = d_normc[(b*3+0)*NPTS + n];
    float ny = d_normc[(b*3+1)*NPTS + n];
    float nz = d_normc[(b*3+2)*NPTS + n];
    int lx = (int)floorf(nx); float fx = nx - (float)lx; int hx = min(lx+1, RES-1);
    int ly = (int)floorf(ny); float fy = ny - (float)ly; int hy = min(ly+1, RES-1);
    int lz = (int)floorf(nz); float fz = nz - (float)lz; int hz = min(lz+1, RES-1);

    float4 acc = make_float4(0.f, 0.f, 0.f, 0.f);
    float sumw = 0.f;
    const float4* gp = (const float4*)d_grid2;
    #pragma unroll
    for (int k = 0; k < 8; k++) {
        int dx = k >> 2, dy = (k >> 1) & 1, dz = k & 1;
        int ix = dx ? hx : lx, iy = dy ? hy : ly, iz = dz ? hz : lz;
        float w = (dx ? fx : 1.f - fx) * (dy ? fy : 1.f - fy) * (dz ? fz : 1.f - fz);
        long row = ((long)(b*NVOX) + (ix*RES + iy)*RES + iz) * (COUT/4);
        float4 v = gp[row + lane];
        acc.x += w*v.x; acc.y += w*v.y; acc.z += w*v.z; acc.w += w*v.w;
        sumw += w;
    }
    float4 a  = ((const float4*)d_A )[b*32 + lane];
    float4 bc = ((const float4*)d_Bc)[b*32 + lane];
    float4 gv;
    gv.x = acc.x*a.x + sumw*bc.x; gv.y = acc.y*a.y + sumw*bc.y;
    gv.z = acc.z*a.z + sumw*bc.z; gv.w = acc.w*a.w + sumw*bc.w;

    float4 pv = ((const float4*)d_pt)[((long)(b*NPTS) + n)*32 + lane];
    float4 pa = ((const float4*)d_ptA)[b*32 + lane];
    float4 pb = ((const float4*)d_ptB)[b*32 + lane];
    float y;
    y = pv.x*pa.x + pb.x; gv.x += y / (1.f + expf(-y));
    y = pv.y*pa.y + pb.y; gv.y += y / (1.f + expf(-y));
    y = pv.z*pa.z + pb.z; gv.z += y / (1.f + expf(-y));
    y = pv.w*pa.w + pb.w; gv.w += y / (1.f + expf(-y));

    long ob = ((long)(b*COUT) + lane*4) * NPTS + n;
    out[ob]          = gv.x;
    out[ob + NPTS]   = gv.y;
    out[ob + 2*NPTS] = gv.z;
    out[ob + 3*NPTS] = gv.w;
}

// ---------------- launch ------------------------------------------------------
extern "C" void kernel_launch(void* const* d_in, const int* in_sizes, int n_in,
                              void* d_out, int out_size) {
    const float* features = (const float*)d_in[0];
    const float* coords   = (const float*)d_in[1];
    const float* conv1_w  = (const float*)d_in[2];
    const float* conv1_b  = (const float*)d_in[3];
    const float* gn1_g    = (const float*)d_in[4];
    const float* gn1_b    = (const float*)d_in[5];
    const float* conv2_w  = (const float*)d_in[6];
    const float* conv2_b  = (const float*)d_in[7];
    const float* gn2_g    = (const float*)d_in[8];
    const float* gn2_b    = (const float*)d_in[9];
    const float* se_w1    = (const float*)d_in[10];
    const float* se_b1    = (const float*)d_in[11];
    const float* se_w2    = (const float*)d_in[12];
    const float* se_b2    = (const float*)d_in[13];
    const float* pt_w     = (const float*)d_in[14];
    const float* pt_b     = (const float*)d_in[15];
    const float* ptgn_g   = (const float*)d_in[16];
    const float* ptgn_b   = (const float*)d_in[17];
    float* out = (float*)d_out;

    cudaFuncSetAttribute(k_conv<CIN,0>,  cudaFuncAttributeMaxDynamicSharedMemorySize, CIN*306*4);
    cudaFuncSetAttribute(k_conv<COUT,1>, cudaFuncAttributeMaxDynamicSharedMemorySize, COUT*306*4);

    k_prep<<<(COUT*27*COUT + 255)/256, 256>>>(conv1_w, conv2_w, pt_w);
    k_zero<<<(BB*NVOX*CIN)/256, 256>>>();
    k_mean<<<BB, 256>>>(coords);
    k_scale<<<BB, 256>>>(coords);
    k_norm<<<(BB*3*NPTS + 255)/256, 256>>>(coords);
    k_scatter<<<(BB*NPTS + 255)/256, 256>>>(features);
    k_div<<<(BB*NVOX*CIN)/256, 256>>>();
    k_conv<CIN,0><<<BB*RES*RES, 256, CIN*306*4>>>(conv1_b);
    k_gstats1<<<BB*64, 256>>>();
    k_gn1<<<(BB*NVOX*COUT)/256, 256>>>(gn1_g, gn1_b);
    k_conv<COUT,1><<<BB*RES*RES, 256, COUT*306*4>>>(conv2_b);
    k_cstats2<<<BB*64, 256>>>();
    k_se<<<BB, 128>>>(se_w1, se_b1, se_w2, se_b2, gn2_g, gn2_b);
    k_pt<<<BB*(NPTS/32), 256>>>(features, pt_b);
    k_ptab<<<(BB*COUT + 255)/256, 256>>>(ptgn_g, ptgn_b);
    k_out<<<(BB*NPTS)/4, 128>>>(out);
}

// round 2
// speedup vs baseline: 1.2995x; 1.2995x over previous
#include <cuda_runtime.h>
#include <math.h>

#define BB 8
#define CIN 64
#define COUT 128
#define NPTS 32768
#define RES 32
#define NVOX (RES*RES*RES)
#define GEPS 1e-5f

// ---------------- scratch (static device globals; no allocation) -------------
__device__ float d_mean[BB*3];
__device__ float d_scale[BB];
__device__ float d_normc[BB*3*NPTS];
__device__ float d_grid0[BB*NVOX*CIN];    //  67 MB  [b][v][ci]
__device__ float d_cnt[BB*NVOX];
__device__ float d_grid1[BB*NVOX*COUT];   // 134 MB  [b][v][o]
__device__ float d_grid2[BB*NVOX*COUT];   // 134 MB
__device__ float d_pt[BB*NPTS*COUT];      // 134 MB  [b][n][o]
__device__ float d_wt1[CIN*27*COUT];      // [(ci*27+t)][o]
__device__ float d_wt2[COUT*27*COUT];
__device__ float d_ptw[CIN*COUT];         // [ci][o]
__device__ float d_gstats1[BB*8*2];
__device__ float d_cstats2[BB*COUT*2];
__device__ float d_ptstats[BB*8*2];
__device__ float d_A[BB*COUT];
__device__ float d_Bc[BB*COUT];
__device__ float d_ptA[BB*COUT];
__device__ float d_ptB[BB*COUT];

// ---------------- prep: weight transposes -----------------------------------
__global__ void k_prep(const float* __restrict__ w1, const float* __restrict__ w2,
                       const float* __restrict__ ptw) {
    int i = blockIdx.x * 256 + threadIdx.x;
    if (i < CIN*27*COUT) {           // wt1[(ci*27+t)*128+o] = w1[(o*CIN+ci)*27+t]
        int o = i & 127; int r = i >> 7; int ci = r / 27, t = r % 27;
        d_wt1[i] = w1[(o*CIN + ci)*27 + t];
    }
    if (i < COUT*27*COUT) {
        int o = i & 127; int r = i >> 7; int ci = r / 27, t = r % 27;
        d_wt2[i] = w2[(o*COUT + ci)*27 + t];
    }
    if (i < CIN*COUT) {              // ptw[ci*128+o] = pt_w[o*CIN+ci]
        int o = i & 127; int ci = i >> 7;
        d_ptw[i] = ptw[o*CIN + ci];
    }
}

__global__ void k_zero() {
    int i = blockIdx.x * 256 + threadIdx.x;   // 16,777,216 threads exactly
    d_grid0[i] = 0.f;
    if (i < BB*NVOX)   d_cnt[i] = 0.f;
    if (i < BB*8*2)    d_gstats1[i] = 0.f;
    if (i < BB*COUT*2) d_cstats2[i] = 0.f;
    if (i < BB*8*2)    d_ptstats[i] = 0.f;
}

// ---------------- voxelize coords --------------------------------------------
__global__ void k_mean(const float* __restrict__ coords) {
    int b = blockIdx.x;
    __shared__ float s[256];
    for (int d = 0; d < 3; d++) {
        float acc = 0.f;
        for (int n = threadIdx.x; n < NPTS; n += 256)
            acc += coords[(b*3 + d)*NPTS + n];
        s[threadIdx.x] = acc; __syncthreads();
        for (int o = 128; o > 0; o >>= 1) {
            if (threadIdx.x < o) s[threadIdx.x] += s[threadIdx.x + o];
            __syncthreads();
        }
        if (threadIdx.x == 0) d_mean[b*3 + d] = s[0] / (float)NPTS;
        __syncthreads();
    }
}

__global__ void k_scale(const float* __restrict__ coords) {
    int b = blockIdx.x;
    float mx = d_mean[b*3], my = d_mean[b*3+1], mz = d_mean[b*3+2];
    __shared__ float s[256];
    float m = 0.f;
    for (int n = threadIdx.x; n < NPTS; n += 256) {
        float x = coords[(b*3+0)*NPTS + n] - mx;
        float y = coords[(b*3+1)*NPTS + n] - my;
        float z = coords[(b*3+2)*NPTS + n] - mz;
        m = fmaxf(m, sqrtf(x*x + y*y + z*z));
    }
    s[threadIdx.x] = m; __syncthreads();
    for (int o = 128; o > 0; o >>= 1) {
        if (threadIdx.x < o) s[threadIdx.x] = fmaxf(s[threadIdx.x], s[threadIdx.x + o]);
        __syncthreads();
    }
    if (threadIdx.x == 0) d_scale[b] = s[0] * 2.f;
}

__global__ void k_norm(const float* __restrict__ coords) {
    int i = blockIdx.x * 256 + threadIdx.x;
    if (i >= BB*3*NPTS) return;
    int b = i / (3*NPTS); int d = (i / NPTS) % 3;
    float t = (coords[i] - d_mean[b*3 + d]) / d_scale[b] + 0.5f;
    d_normc[i] = fminf(fmaxf(t * (float)RES, 0.f), (float)(RES - 1));
}

// ---------------- scatter-mean voxelization ----------------------------------
__global__ void k_scatter(const float* __restrict__ feat) {
    int p = blockIdx.x * 256 + threadIdx.x;
    if (p >= BB*NPTS) return;
    int b = p >> 15, n = p & (NPTS - 1);
    int ix = min(max((int)rintf(d_normc[(b*3+0)*NPTS + n]), 0), RES-1);
    int iy = min(max((int)rintf(d_normc[(b*3+1)*NPTS + n]), 0), RES-1);
    int iz = min(max((int)rintf(d_normc[(b*3+2)*NPTS + n]), 0), RES-1);
    int vid = (ix*RES + iy)*RES + iz;
    float* row = &d_grid0[(long)(b*NVOX + vid) * CIN];
    #pragma unroll 4
    for (int c = 0; c < CIN; c++)
        atomicAdd(&row[c], feat[((long)(b*CIN) + c)*NPTS + n]);
    atomicAdd(&d_cnt[b*NVOX + vid], 1.f);
}

__global__ void k_div() {
    int i = blockIdx.x * 256 + threadIdx.x;   // B*NVOX*CIN threads
    float c = d_cnt[i / CIN];
    d_grid0[i] = d_grid0[i] / fmaxf(c, 1.f);
}

// ---------------- 3x3x3 conv, channels-last, z-line per block ----------------
// STAGE 0: grid0(CIN) -> grid1 with wt1; STAGE 1: grid1(COUT) -> grid2 with wt2
// SMEM rows padded to 36 floats so z-slices can be read with LDS.128 broadcast.
// Weight loads are software-pipelined one (ci,xy) iteration ahead.
template<int CI, int STAGE>
__global__ void k_conv(const float* __restrict__ bias) {
    extern __shared__ float sm[];                      // [ci*9+xy][36]
    const float* __restrict__ gin  = (STAGE == 0) ? d_grid0 : d_grid1;
    float*       __restrict__ gout = (STAGE == 0) ? d_grid1 : d_grid2;
    const float* __restrict__ wt   = (STAGE == 0) ? d_wt1   : d_wt2;

    int blk = blockIdx.x;
    int b = blk >> 10, xr = (blk >> 5) & 31, yr = blk & 31;

    const int TOT = CI * 306;                          // 9 * 34 * CI valid entries
    for (int e = threadIdx.x; e < TOT; e += 256) {
        int ci = e % CI; int rest = e / CI;
        int zz = rest % 34; int xy = rest / 34;
        int gx = xr - 1 + xy / 3, gy = yr - 1 + xy % 3, gz = zz - 1;
        float v = 0.f;
        if (gx >= 0 && gx < RES && gy >= 0 && gy < RES && gz >= 0 && gz < RES)
            v = gin[((long)(b*NVOX) + (gx*RES + gy)*RES + gz) * CI + ci];
        sm[(ci*9 + xy)*36 + zz] = v;
    }
    __syncthreads();

    int o = threadIdx.x & 127, h = threadIdx.x >> 7, z0 = h * 16;
    float acc[16];
    float bv = bias[o];
    #pragma unroll
    for (int z = 0; z < 16; z++) acc[z] = bv;

    const int NI = CI * 9;
    // prefetch weights for ii = 0
    float wa = wt[o], wb = wt[COUT + o], wc = wt[2*COUT + o];

    #pragma unroll 1
    for (int ii = 0; ii < NI; ii++) {
        float cw0 = wa, cw1 = wb, cw2 = wc;
        if (ii + 1 < NI) {                 // prefetch next iteration's weights
            const float* wp = &wt[(ii + 1) * 3 * COUT + o];
            wa = wp[0]; wb = wp[COUT]; wc = wp[2*COUT];
        }
        // vectorized broadcast loads: 5 x float4 = 20 floats (indices 16..35 ok, padded)
        float4 v4[5];
        const float4* ip4 = (const float4*)(sm + ii*36 + z0);
        #pragma unroll
        for (int j = 0; j < 5; j++) v4[j] = ip4[j];
        const float* inr = (const float*)v4;
        #pragma unroll
        for (int z = 0; z < 16; z++) {
            float a = acc[z];
            a = fmaf(cw0, inr[z],     a);
            a = fmaf(cw1, inr[z + 1], a);
            a = fmaf(cw2, inr[z + 2], a);
            acc[z] = a;
        }
    }
    long base = ((long)(b*NVOX) + (xr*RES + yr)*RES + z0) * COUT + o;
    #pragma unroll
    for (int z = 0; z < 16; z++) gout[base + (long)z * COUT] = acc[z];
}

// ---------------- GN1 stats + normalize+swish --------------------------------
__global__ void k_gstats1() {
    int b = blockIdx.x >> 6, ch = blockIdx.x & 63;     // 512 voxels per chunk
    int c = threadIdx.x & 127, l2 = threadIdx.x >> 7;
    long base = ((long)b*NVOX + ch*512) * COUT;
    float s = 0.f, q = 0.f;
    for (int v = l2; v < 512; v += 2) {
        float x = d_grid1[base + (long)v*COUT + c];
        s += x; q += x*x;
    }
    __shared__ float ss[256], sq[256];
    ss[threadIdx.x] = s; sq[threadIdx.x] = q;
    __syncthreads();
    if (threadIdx.x < 8) {
        float S = 0.f, Q = 0.f;
        for (int j = 0; j < 16; j++) {
            int cc = threadIdx.x*16 + j;
            S += ss[cc] + ss[cc+128]; Q += sq[cc] + sq[cc+128];
        }
        atomicAdd(&d_gstats1[(b*8 + threadIdx.x)*2 + 0], S);
        atomicAdd(&d_gstats1[(b*8 + threadIdx.x)*2 + 1], Q);
    }
}

__global__ void k_gn1(const float* __restrict__ g, const float* __restrict__ bt) {
    int i = blockIdx.x * 256 + threadIdx.x;            // B*NVOX*COUT threads
    int c = i & 127; int b = i >> 22;                  // i/(NVOX*128) = i>>22
    int gr = c >> 4;
    float S = d_gstats1[(b*8 + gr)*2], Q = d_gstats1[(b*8 + gr)*2 + 1];
    const float cnt = (float)NVOX * 16.f;
    float mu = S / cnt; float var = Q / cnt - mu*mu;
    float rs = rsqrtf(var + GEPS);
    float y = (d_grid1[i] - mu) * rs * g[c] + bt[c];
    d_grid1[i] = y / (1.f + expf(-y));
}

// ---------------- GN2 per-channel stats (for GN + SE fold) -------------------
__global__ void k_cstats2() {
    int b = blockIdx.x >> 6, ch = blockIdx.x & 63;
    int c = threadIdx.x & 127, l2 = threadIdx.x >> 7;
    long base = ((long)b*NVOX + ch*512) * COUT;
    float s = 0.f, q = 0.f;
    for (int v = l2; v < 512; v += 2) {
        float x = d_grid2[base + (long)v*COUT + c];
        s += x; q += x*x;
    }
    __shared__ float ss[256], sq[256];
    ss[threadIdx.x] = s; sq[threadIdx.x] = q;
    __syncthreads();
    if (threadIdx.x < 128) {
        atomicAdd(&d_cstats2[(b*COUT + c)*2 + 0], ss[c] + ss[c+128]);
        atomicAdd(&d_cstats2[(b*COUT + c)*2 + 1], sq[c] + sq[c+128]);
    }
}

// ---------------- SE + fold GN2*SE into per-(b,c) affine ---------------------
__global__ void k_se(const float* __restrict__ w1, const float* __restrict__ b1,
                     const float* __restrict__ w2, const float* __restrict__ b2,
                     const float* __restrict__ gamma, const float* __restrict__ beta) {
    int b = blockIdx.x; int c = threadIdx.x;
    __shared__ float s[128], gmu[8], grs[8], s1[16];
    const float cnt = (float)NVOX;
    if (c < 8) {
        float S = 0.f, Q = 0.f;
        for (int j = 0; j < 16; j++) {
            S += d_cstats2[(b*COUT + c*16 + j)*2 + 0];
            Q += d_cstats2[(b*COUT + c*16 + j)*2 + 1];
        }
        float gc = cnt * 16.f;
        float mu = S / gc; float var = Q / gc - mu*mu;
        gmu[c] = mu; grs[c] = rsqrtf(var + GEPS);
    }
    __syncthreads();
    int gr = c >> 4;
    float mu = gmu[gr], rs = grs[gr];
    float csum = d_cstats2[(b*COUT + c)*2];
    s[c] = (csum / cnt - mu) * rs * gamma[c] + beta[c];   // pooled mean of gn2 out
    __syncthreads();
    if (c < 16) {
        float a = b1[c];
        for (int j = 0; j < 128; j++) a += w1[c*128 + j] * s[j];
        s1[c] = fmaxf(a, 0.f);
    }
    __syncthreads();
    float a2 = b2[c];
    for (int j = 0; j < 16; j++) a2 += w2[c*16 + j] * s1[j];
    float se = 1.f / (1.f + expf(-a2));
    float rg = rs * gamma[c];
    d_A [b*COUT + c] = rg * se;
    d_Bc[b*COUT + c] = (beta[c] - mu * rg) * se;
}

// ---------------- point branch 1x1 conv + stats ------------------------------
__global__ void k_pt(const float* __restrict__ feat, const float* __restrict__ ptb) {
    int blk = blockIdx.x;
    int b = blk >> 10, n0 = (blk & 1023) * 32;
    __shared__ float fs[CIN*32];       // [ci][nn]
    __shared__ float so[32*COUT];      // [nn][o]
    __shared__ float ss[256], sq[256];
    for (int e = threadIdx.x; e < CIN*32; e += 256) {
        int ci = e >> 5, nn = e & 31;
        fs[e] = feat[((long)(b*CIN) + ci)*NPTS + n0 + nn];
    }
    __syncthreads();
    int o = threadIdx.x & 127, h = threadIdx.x >> 7;
    float acc[16];
    float bv = ptb[o];
    #pragma unroll
    for (int j = 0; j < 16; j++) acc[j] = bv;
    for (int ci = 0; ci < CIN; ci++) {
        float w = d_ptw[ci*COUT + o];
        #pragma unroll
        for (int j = 0; j < 16; j++)
            acc[j] = fmaf(w, fs[ci*32 + h*16 + j], acc[j]);
    }
    float s = 0.f, q = 0.f;
    #pragma unroll
    for (int j = 0; j < 16; j++) {
        s += acc[j]; q += acc[j]*acc[j];
        so[(h*16 + j)*COUT + o] = acc[j];
    }
    ss[threadIdx.x] = s; sq[threadIdx.x] = q;
    __syncthreads();
    if (threadIdx.x < 8) {
        float S = 0.f, Q = 0.f;
        for (int j = 0; j < 16; j++) {
            int cc = threadIdx.x*16 + j;
            S += ss[cc] + ss[cc+128]; Q += sq[cc] + sq[cc+128];
        }
        atomicAdd(&d_ptstats[(b*8 + threadIdx.x)*2 + 0], S);
        atomicAdd(&d_ptstats[(b*8 + threadIdx.x)*2 + 1], Q);
    }
    for (int e = threadIdx.x; e < 32*COUT; e += 256) {
        int nn = e >> 7, oo = e & 127;
        d_pt[((long)(b*NPTS) + n0 + nn)*COUT + oo] = so[e];
    }
}

__global__ void k_ptab(const float* __restrict__ g, const float* __restrict__ bt) {
    int i = blockIdx.x * 256 + threadIdx.x;
    if (i >= BB*COUT) return;
    int b = i >> 7, c = i & 127, gr = c >> 4;
    const float cnt = 16.f * (float)NPTS;
    float S = d_ptstats[(b*8 + gr)*2], Q = d_ptstats[(b*8 + gr)*2 + 1];
    float mu = S / cnt, var = Q / cnt - mu*mu, rs = rsqrtf(var + GEPS);
    d_ptA[i] = rs * g[c];
    d_ptB[i] = bt[c] - mu * rs * g[c];
}

// ---------------- trilinear devoxelize + point add -> out --------------------
__global__ void k_out(float* __restrict__ out) {
    int p = blockIdx.x * 4 + (threadIdx.x >> 5);
    int lane = threadIdx.x & 31;
    int b = p >> 15, n = p & (NPTS - 1);
    float nx = d_normc[(b*3+0)*NPTS + n];
    float ny = d_normc[(b*3+1)*NPTS + n];
    float nz = d_normc[(b*3+2)*NPTS + n];
    int lx = (int)floorf(nx); float fx = nx - (float)lx; int hx = min(lx+1, RES-1);
    int ly = (int)floorf(ny); float fy = ny - (float)ly; int hy = min(ly+1, RES-1);
    int lz = (int)floorf(nz); float fz = nz - (float)lz; int hz = min(lz+1, RES-1);

    float4 acc = make_float4(0.f, 0.f, 0.f, 0.f);
    float sumw = 0.f;
    const float4* gp = (const float4*)d_grid2;
    #pragma unroll
    for (int k = 0; k < 8; k++) {
        int dx = k >> 2, dy = (k >> 1) & 1, dz = k & 1;
        int ix = dx ? hx : lx, iy = dy ? hy : ly, iz = dz ? hz : lz;
        float w = (dx ? fx : 1.f - fx) * (dy ? fy : 1.f - fy) * (dz ? fz : 1.f - fz);
        long row = ((long)(b*NVOX) + (ix*RES + iy)*RES + iz) * (COUT/4);
        float4 v = gp[row + lane];
        acc.x += w*v.x; acc.y += w*v.y; acc.z += w*v.z; acc.w += w*v.w;
        sumw += w;
    }
    float4 a  = ((const float4*)d_A )[b*32 + lane];
    float4 bc = ((const float4*)d_Bc)[b*32 + lane];
    float4 gv;
    gv.x = acc.x*a.x + sumw*bc.x; gv.y = acc.y*a.y + sumw*bc.y;
    gv.z = acc.z*a.z + sumw*bc.z; gv.w = acc.w*a.w + sumw*bc.w;

    float4 pv = ((const float4*)d_pt)[((long)(b*NPTS) + n)*32 + lane];
    float4 pa = ((const float4*)d_ptA)[b*32 + lane];
    float4 pb = ((const float4*)d_ptB)[b*32 + lane];
    float y;
    y = pv.x*pa.x + pb.x; gv.x += y / (1.f + expf(-y));
    y = pv.y*pa.y + pb.y; gv.y += y / (1.f + expf(-y));
    y = pv.z*pa.z + pb.z; gv.z += y / (1.f + expf(-y));
    y = pv.w*pa.w + pb.w; gv.w += y / (1.f + expf(-y));

    long ob = ((long)(b*COUT) + lane*4) * NPTS + n;
    out[ob]          = gv.x;
    out[ob + NPTS]   = gv.y;
    out[ob + 2*NPTS] = gv.z;
    out[ob + 3*NPTS] = gv.w;
}

// ---------------- launch ------------------------------------------------------
extern "C" void kernel_launch(void* const* d_in, const int* in_sizes, int n_in,
                              void* d_out, int out_size) {
    const float* features = (const float*)d_in[0];
    const float* coords   = (const float*)d_in[1];
    const float* conv1_w  = (const float*)d_in[2];
    const float* conv1_b  = (const float*)d_in[3];
    const float* gn1_g    = (const float*)d_in[4];
    const float* gn1_b    = (const float*)d_in[5];
    const float* conv2_w  = (const float*)d_in[6];
    const float* conv2_b  = (const float*)d_in[7];
    const float* gn2_g    = (const float*)d_in[8];
    const float* gn2_b    = (const float*)d_in[9];
    const float* se_w1    = (const float*)d_in[10];
    const float* se_b1    = (const float*)d_in[11];
    const float* se_w2    = (const float*)d_in[12];
    const float* se_b2    = (const float*)d_in[13];
    const float* pt_w     = (const float*)d_in[14];
    const float* pt_b     = (const float*)d_in[15];
    const float* ptgn_g   = (const float*)d_in[16];
    const float* ptgn_b   = (const float*)d_in[17];
    float* out = (float*)d_out;

    cudaFuncSetAttribute(k_conv<CIN,0>,  cudaFuncAttributeMaxDynamicSharedMemorySize, CIN*9*36*4);
    cudaFuncSetAttribute(k_conv<COUT,1>, cudaFuncAttributeMaxDynamicSharedMemorySize, COUT*9*36*4);

    k_prep<<<(COUT*27*COUT + 255)/256, 256>>>(conv1_w, conv2_w, pt_w);
    k_zero<<<(BB*NVOX*CIN)/256, 256>>>();
    k_mean<<<BB, 256>>>(coords);
    k_scale<<<BB, 256>>>(coords);
    k_norm<<<(BB*3*NPTS + 255)/256, 256>>>(coords);
    k_scatter<<<(BB*NPTS + 255)/256, 256>>>(features);
    k_div<<<(BB*NVOX*CIN)/256, 256>>>();
    k_conv<CIN,0><<<BB*RES*RES, 256, CIN*9*36*4>>>(conv1_b);
    k_gstats1<<<BB*64, 256>>>();
    k_gn1<<<(BB*NVOX*COUT)/256, 256>>>(gn1_g, gn1_b);
    k_conv<COUT,1><<<BB*RES*RES, 256, COUT*9*36*4>>>(conv2_b);
    k_cstats2<<<BB*64, 256>>>();
    k_se<<<BB, 128>>>(se_w1, se_b1, se_w2, se_b2, gn2_g, gn2_b);
    k_pt<<<BB*(NPTS/32), 256>>>(features, pt_b);
    k_ptab<<<(BB*COUT + 255)/256, 256>>>(ptgn_g, ptgn_b);
    k_out<<<(BB*NPTS)/4, 128>>>(out);
}